// round 17
// baseline (speedup 1.0000x reference)
#include <cuda_runtime.h>
#include <cuda_bf16.h>
#include <cstdint>
#include <cstddef>

// ---------------- problem constants ----------------
#define NN     50000
#define EE     500000
#define NPG    6250
#define NB     8
#define OCOLS  532     // output row stride (2*266)
#define NFEAT  266     // per-node feature count (10 + 4*64)
#define NSPLIT 13
#define PS     481
// output row layout (logical): [feat(10) h0(64) h1(64) h2(64) h3(64) | rep(266)]

// ---------------- device scratch ----------------
__device__ __align__(16) float g_h     [NN * 64];
__device__ __align__(16) float g_hni   [NN * 128];
__device__ __align__(16) float g_hnj   [NN * 128];
__device__ __align__(16) float g_hnode [NN * 128];
__device__ __align__(16) float g_hatt  [NN * 128];
__device__ int   g_deg   [NN];
__device__ int   g_rowptr[NN + 1];
__device__ int   g_cursor[NN];
__device__ int   g_bsum  [256];
__device__ __align__(16) unsigned int g_edata[(size_t)EE * 8];  // CSR-ordered edge records
__device__ __align__(16) float g_table [217 * 128];
__device__ __align__(16) float g_crcrp [5 * 128];
__device__ __align__(16) float g_gmax  [NB * NFEAT];
__device__ __align__(16) float g_pool  [NB * 5 * NSPLIT * 64];

// ---------------- tf32 helpers ----------------
__device__ __forceinline__ uint32_t f2tf(float x) {
    uint32_t r;
    asm("cvt.rna.tf32.f32 %0, %1;" : "=r"(r) : "f"(x));
    return r;
}
__device__ __forceinline__ uint4 f4tf(float4 v) {
    return make_uint4(f2tf(v.x), f2tf(v.y), f2tf(v.z), f2tf(v.w));
}
__device__ __forceinline__ void mma_tf32(float c[4], const uint32_t a[4], const uint32_t b[2]) {
    asm volatile(
        "mma.sync.aligned.m16n8k8.row.col.f32.tf32.tf32.f32 "
        "{%0,%1,%2,%3}, {%4,%5,%6,%7}, {%8,%9}, {%0,%1,%2,%3};"
        : "+f"(c[0]), "+f"(c[1]), "+f"(c[2]), "+f"(c[3])
        : "r"(a[0]), "r"(a[1]), "r"(a[2]), "r"(a[3]), "r"(b[0]), "r"(b[1]));
}

// ---------------- feature-encoder MLP (feat -> h0); writes out cols 0..73 ---
__global__ __launch_bounds__(256) void fe_mlp_k(
    const float* __restrict__ feat, const float* __restrict__ W0,
    const float* __restrict__ b0,   const float* __restrict__ W1,
    const float* __restrict__ b1,   float* __restrict__ h,
    float* __restrict__ out)
{
    __shared__ float sW0[640], sb0[64], sW1[4096], sb1[64];
    int tid = threadIdx.x;
    for (int i = tid; i < 640;  i += 256) sW0[i] = W0[i];
    for (int i = tid; i < 4096; i += 256) sW1[i] = W1[i];
    if (tid < 64) { sb0[tid] = b0[tid]; sb1[tid] = b1[tid]; }
    __syncthreads();
    int n = blockIdx.x * 256 + tid;
    if (n >= NN) return;
    float f[10];
#pragma unroll
    for (int i = 0; i < 10; i++) {
        f[i] = feat[n * 10 + i];
        out[(size_t)n * OCOLS + i] = f[i];
    }
    float hid[64];
#pragma unroll
    for (int c = 0; c < 64; c++) {
        float s = sb0[c];
#pragma unroll
        for (int k = 0; k < 10; k++) s += f[k] * sW0[k * 64 + c];
        hid[c] = fmaxf(s, 0.f);
    }
    for (int c = 0; c < 64; c++) {
        float s = sb1[c];
#pragma unroll
        for (int k = 0; k < 64; k++) s += hid[k] * sW1[k * 64 + c];
        h[(size_t)n * 64 + c] = s;
        out[(size_t)n * OCOLS + 10 + c] = s;
    }
}

// ---------------- CSR build ----------------
__global__ void zero_int_k(int* p, int n) {
    int i = blockIdx.x * 256 + threadIdx.x;
    if (i < n) p[i] = 0;
}
__global__ void hist_k(const int* __restrict__ dst, int* deg) {
    int e = blockIdx.x * 256 + threadIdx.x;
    if (e < EE) atomicAdd(&deg[dst[e]], 1);
}
__global__ void scan_partial_k(const int* __restrict__ deg, int* bsum) {
    __shared__ int s[256];
    int i = blockIdx.x * 256 + threadIdx.x;
    s[threadIdx.x] = (i < NN) ? deg[i] : 0;
    __syncthreads();
#pragma unroll
    for (int o = 128; o; o >>= 1) {
        if (threadIdx.x < o) s[threadIdx.x] += s[threadIdx.x + o];
        __syncthreads();
    }
    if (threadIdx.x == 0) bsum[blockIdx.x] = s[0];
}
__global__ void scan_bsum_k(int* bsum, int nb) {
    __shared__ int s[256];
    int t = threadIdx.x;
    int v = (t < nb) ? bsum[t] : 0;
    s[t] = v;
    __syncthreads();
#pragma unroll
    for (int o = 1; o < 256; o <<= 1) {
        int x = (t >= o) ? s[t - o] : 0;
        __syncthreads();
        s[t] += x;
        __syncthreads();
    }
    if (t < nb) bsum[t] = s[t] - v;   // exclusive
}
__global__ void scan_final_k(const int* __restrict__ deg, const int* __restrict__ bsum,
                             int* rowptr, int* cursor) {
    __shared__ int s[256];
    int i = blockIdx.x * 256 + threadIdx.x;
    int v = (i < NN) ? deg[i] : 0;
    s[threadIdx.x] = v;
    __syncthreads();
#pragma unroll
    for (int o = 1; o < 256; o <<= 1) {
        int x = (threadIdx.x >= o) ? s[threadIdx.x - o] : 0;
        __syncthreads();
        s[threadIdx.x] += x;
        __syncthreads();
    }
    if (i < NN) {
        int off = bsum[blockIdx.x] + s[threadIdx.x] - v;
        rowptr[i] = off;
        cursor[i] = off;
    }
    if (i == NN - 1) rowptr[NN] = EE;
}
// scatter: packs per-edge record (CSR order): [src, tr, a0, a1, p0, p1, p2, 0]
__global__ void scatter_k(const int* __restrict__ dst, const int* __restrict__ src,
                          const int* __restrict__ etype, const int* __restrict__ rid,
                          const float* __restrict__ att_rc, const float* __restrict__ att_rp,
                          int* cursor, unsigned int* __restrict__ edata) {
    int e = blockIdx.x * 256 + threadIdx.x;
    if (e < EE) {
        int pos = atomicAdd(&cursor[dst[e]], 1);
        uint4 r0, r1;
        r0.x = (unsigned int)src[e];
        r0.y = (unsigned int)(etype[e] * 31 + rid[e]);
        r0.z = __float_as_uint(att_rc[e * 2]);
        r0.w = __float_as_uint(att_rc[e * 2 + 1]);
        r1.x = __float_as_uint(att_rp[e * 3]);
        r1.y = __float_as_uint(att_rp[e * 3 + 1]);
        r1.z = __float_as_uint(att_rp[e * 3 + 2]);
        r1.w = 0u;
        *(uint4*)(edata + (size_t)pos * 8)     = r0;
        *(uint4*)(edata + (size_t)pos * 8 + 4) = r1;
    }
}

// ---------------- per-layer f_fij precompute ----------------
__global__ void precompute_fij_k(
    const float* __restrict__ etype_emb, const float* __restrict__ rid_emb,
    const float* __restrict__ rc_W, const float* __restrict__ rp_W,
    const float* __restrict__ rc_b, const float* __restrict__ rp_b,
    const float* __restrict__ Wf,   const float* __restrict__ ebias,
    float* __restrict__ table, float* __restrict__ crcrp)
{
    int row = blockIdx.x;         // 0..221
    int c   = threadIdx.x;        // 0..127
    __shared__ float v[64];
    if (threadIdx.x < 64) {
        int k = threadIdx.x;
        float val;
        if (row < 217) {
            int et = row / 31, r = row % 31;
            val = etype_emb[et * 64 + k] + rid_emb[r * 64 + k] + rc_b[k] + rp_b[k];
        } else if (row < 219) {
            val = rc_W[(row - 217) * 64 + k];
        } else {
            val = rp_W[(row - 219) * 64 + k];
        }
        v[k] = val;
    }
    __syncthreads();
    float s = 0.f;
#pragma unroll
    for (int k = 0; k < 64; k++) s += v[k] * Wf[k * 128 + c];
    if (row < 217) table[row * 128 + c] = s + ebias[c];
    else           crcrp[(row - 217) * 128 + c] = s;
}

// ---------------- tf32 3-way projection GEMM: [128,64] tile @ [64,128] ------
#define LDA_P 68
#define LDW_P 132
__global__ __launch_bounds__(256) void proj3_k(
    const float* __restrict__ A,
    const float* __restrict__ W0, const float* __restrict__ W1, const float* __restrict__ W2,
    float* __restrict__ C0, float* __restrict__ C1, float* __restrict__ C2,
    int nrows)
{
    const float* W = (blockIdx.y == 0) ? W0 : (blockIdx.y == 1) ? W1 : W2;
    float*       C = (blockIdx.y == 0) ? C0 : (blockIdx.y == 1) ? C1 : C2;
    extern __shared__ uint32_t smu[];
    uint32_t* As = smu;                 // [128][LDA_P]
    uint32_t* Ws = smu + 128 * LDA_P;   // [64][LDW_P]
    int tid  = threadIdx.x;
    int row0 = blockIdx.x * 128;
#pragma unroll
    for (int i = 0; i < 8; i++) {
        int idx = tid + i * 256;
        int r = idx >> 4, c4 = idx & 15;
        float4 v = make_float4(0.f, 0.f, 0.f, 0.f);
        if (row0 + r < nrows) v = *(const float4*)(A + (size_t)(row0 + r) * 64 + c4 * 4);
        *(uint4*)(As + r * LDA_P + c4 * 4) = f4tf(v);
    }
#pragma unroll
    for (int i = 0; i < 8; i++) {
        int idx = tid + i * 256;
        int r = idx >> 5, c4 = idx & 31;
        *(uint4*)(Ws + r * LDW_P + c4 * 4) = f4tf(*(const float4*)(W + idx * 4));
    }
    __syncthreads();
    int w = tid >> 5, lane = tid & 31;
    int gr = lane >> 2, gc = lane & 3;
    int m0 = (w & 3) * 32, n0 = (w >> 2) * 64;
    float acc[2][8][4];
#pragma unroll
    for (int mt = 0; mt < 2; mt++)
#pragma unroll
        for (int nt = 0; nt < 8; nt++)
            acc[mt][nt][0] = acc[mt][nt][1] = acc[mt][nt][2] = acc[mt][nt][3] = 0.f;
#pragma unroll
    for (int kt = 0; kt < 8; kt++) {
        int k0 = kt * 8;
        uint32_t a[2][4], b[8][2];
#pragma unroll
        for (int mt = 0; mt < 2; mt++) {
            int rb = m0 + mt * 16 + gr;
            a[mt][0] = As[rb * LDA_P + k0 + gc];
            a[mt][1] = As[(rb + 8) * LDA_P + k0 + gc];
            a[mt][2] = As[rb * LDA_P + k0 + gc + 4];
            a[mt][3] = As[(rb + 8) * LDA_P + k0 + gc + 4];
        }
#pragma unroll
        for (int nt = 0; nt < 8; nt++) {
            int cb = n0 + nt * 8 + gr;
            b[nt][0] = Ws[(k0 + gc) * LDW_P + cb];
            b[nt][1] = Ws[(k0 + gc + 4) * LDW_P + cb];
        }
#pragma unroll
        for (int mt = 0; mt < 2; mt++)
#pragma unroll
            for (int nt = 0; nt < 8; nt++)
                mma_tf32(acc[mt][nt], a[mt], b[nt]);
    }
#pragma unroll
    for (int mt = 0; mt < 2; mt++) {
        int r  = row0 + m0 + mt * 16 + gr;
        int r8 = r + 8;
#pragma unroll
        for (int nt = 0; nt < 8; nt++) {
            int c = n0 + nt * 8 + 2 * gc;
            if (r < nrows)
                *(float2*)(C + (size_t)r * 128 + c)  = make_float2(acc[mt][nt][0], acc[mt][nt][1]);
            if (r8 < nrows)
                *(float2*)(C + (size_t)r8 * 128 + c) = make_float2(acc[mt][nt][2], acc[mt][nt][3]);
        }
    }
}

// ---------------- tf32 fused node MLP; writes h and out[:, ocol..ocol+63] ---
#define LDH_M 132
#define LDW2_M 68
__global__ __launch_bounds__(256) void mlp_fused_k(
    const float* __restrict__ hatt,
    const float* __restrict__ Wm0, const float* __restrict__ bm0,
    const float* __restrict__ Wm1, const float* __restrict__ bm1,
    float* __restrict__ h, float* __restrict__ out, int ocol, int nrows)
{
    extern __shared__ uint32_t smu[];
    uint32_t* As = smu;                 // [128][LDH_M]
    uint32_t* Ws = smu + 128 * LDH_M;
    int tid  = threadIdx.x;
    int row0 = blockIdx.x * 128;
#pragma unroll
    for (int i = 0; i < 16; i++) {
        int idx = tid + i * 256;
        int r = idx >> 5, c4 = idx & 31;
        float4 v = make_float4(0.f, 0.f, 0.f, 0.f);
        if (row0 + r < nrows) v = *(const float4*)(hatt + (size_t)(row0 + r) * 128 + c4 * 4);
        *(uint4*)(As + r * LDH_M + c4 * 4) = f4tf(v);
    }
#pragma unroll
    for (int i = 0; i < 16; i++) {
        int idx = tid + i * 256;
        int r = idx >> 5, c4 = idx & 31;
        *(uint4*)(Ws + r * LDH_M + c4 * 4) = f4tf(*(const float4*)(Wm0 + idx * 4));
    }
    __syncthreads();
    int w = tid >> 5, lane = tid & 31;
    int gr = lane >> 2, gc = lane & 3;
    int m0 = (w & 3) * 32;
    {
        int n0 = (w >> 2) * 64;
        float acc[2][8][4];
#pragma unroll
        for (int mt = 0; mt < 2; mt++)
#pragma unroll
            for (int nt = 0; nt < 8; nt++)
                acc[mt][nt][0] = acc[mt][nt][1] = acc[mt][nt][2] = acc[mt][nt][3] = 0.f;
#pragma unroll
        for (int kt = 0; kt < 16; kt++) {
            int k0 = kt * 8;
            uint32_t a[2][4], b[8][2];
#pragma unroll
            for (int mt = 0; mt < 2; mt++) {
                int rb = m0 + mt * 16 + gr;
                a[mt][0] = As[rb * LDH_M + k0 + gc];
                a[mt][1] = As[(rb + 8) * LDH_M + k0 + gc];
                a[mt][2] = As[rb * LDH_M + k0 + gc + 4];
                a[mt][3] = As[(rb + 8) * LDH_M + k0 + gc + 4];
            }
#pragma unroll
            for (int nt = 0; nt < 8; nt++) {
                int cb = n0 + nt * 8 + gr;
                b[nt][0] = Ws[(k0 + gc) * LDH_M + cb];
                b[nt][1] = Ws[(k0 + gc + 4) * LDH_M + cb];
            }
#pragma unroll
            for (int mt = 0; mt < 2; mt++)
#pragma unroll
                for (int nt = 0; nt < 8; nt++)
                    mma_tf32(acc[mt][nt], a[mt], b[nt]);
        }
        __syncthreads();
#pragma unroll
        for (int mt = 0; mt < 2; mt++) {
            int rb  = m0 + mt * 16 + gr;
#pragma unroll
            for (int nt = 0; nt < 8; nt++) {
                int c = n0 + nt * 8 + 2 * gc;
                float b0v = bm0[c], b1v = bm0[c + 1];
                As[rb * LDH_M + c]           = f2tf(fmaxf(acc[mt][nt][0] + b0v, 0.f));
                As[rb * LDH_M + c + 1]       = f2tf(fmaxf(acc[mt][nt][1] + b1v, 0.f));
                As[(rb + 8) * LDH_M + c]     = f2tf(fmaxf(acc[mt][nt][2] + b0v, 0.f));
                As[(rb + 8) * LDH_M + c + 1] = f2tf(fmaxf(acc[mt][nt][3] + b1v, 0.f));
            }
        }
    }
#pragma unroll
    for (int i = 0; i < 8; i++) {
        int idx = tid + i * 256;
        int r = idx >> 4, c4 = idx & 15;
        *(uint4*)(Ws + r * LDW2_M + c4 * 4) = f4tf(*(const float4*)(Wm1 + idx * 4));
    }
    __syncthreads();
    {
        int n0 = (w >> 2) * 32;
        float acc[2][4][4];
#pragma unroll
        for (int mt = 0; mt < 2; mt++)
#pragma unroll
            for (int nt = 0; nt < 4; nt++)
                acc[mt][nt][0] = acc[mt][nt][1] = acc[mt][nt][2] = acc[mt][nt][3] = 0.f;
#pragma unroll
        for (int kt = 0; kt < 16; kt++) {
            int k0 = kt * 8;
            uint32_t a[2][4], b[4][2];
#pragma unroll
            for (int mt = 0; mt < 2; mt++) {
                int rb = m0 + mt * 16 + gr;
                a[mt][0] = As[rb * LDH_M + k0 + gc];
                a[mt][1] = As[(rb + 8) * LDH_M + k0 + gc];
                a[mt][2] = As[rb * LDH_M + k0 + gc + 4];
                a[mt][3] = As[(rb + 8) * LDH_M + k0 + gc + 4];
            }
#pragma unroll
            for (int nt = 0; nt < 4; nt++) {
                int cb = n0 + nt * 8 + gr;
                b[nt][0] = Ws[(k0 + gc) * LDW2_M + cb];
                b[nt][1] = Ws[(k0 + gc + 4) * LDW2_M + cb];
            }
#pragma unroll
            for (int mt = 0; mt < 2; mt++)
#pragma unroll
                for (int nt = 0; nt < 4; nt++)
                    mma_tf32(acc[mt][nt], a[mt], b[nt]);
        }
#pragma unroll
        for (int mt = 0; mt < 2; mt++) {
            int r  = row0 + m0 + mt * 16 + gr;
            int r8 = r + 8;
#pragma unroll
            for (int nt = 0; nt < 4; nt++) {
                int c = n0 + nt * 8 + 2 * gc;
                float b0v = bm1[c], b1v = bm1[c + 1];
                if (r < nrows) {
                    float2 prev = *(const float2*)(h + (size_t)r * 64 + c);
                    float2 o = make_float2(acc[mt][nt][0] + b0v + prev.x,
                                           acc[mt][nt][1] + b1v + prev.y);
                    *(float2*)(h + (size_t)r * 64 + c) = o;
                    *(float2*)(out + (size_t)r * OCOLS + ocol + c) = o;
                }
                if (r8 < nrows) {
                    float2 prev = *(const float2*)(h + (size_t)r8 * 64 + c);
                    float2 o = make_float2(acc[mt][nt][2] + b0v + prev.x,
                                           acc[mt][nt][3] + b1v + prev.y);
                    *(float2*)(h + (size_t)r8 * 64 + c) = o;
                    *(float2*)(out + (size_t)r8 * OCOLS + ocol + c) = o;
                }
            }
        }
    }
}

// ---------------- fused edge attention + online softmax + aggregation -------
// Dual-stream: warp per dst node, each HALF-warp processes one edge per
// iteration (lane q=lane&15 owns channels 8q..8q+7). Two independent online
// softmax states merged at the end via shfl.xor(16). Exact math.
__global__ __launch_bounds__(256) void attn_agg_k(
    const float* __restrict__ hni, const float* __restrict__ hnj,
    const float* __restrict__ hnode,
    const float* __restrict__ table, const float* __restrict__ crcrp,
    const float* __restrict__ attn,
    const int* __restrict__ rowptr, const unsigned int* __restrict__ edata,
    float* __restrict__ hatt)
{
    __shared__ float sC[640], sAttn[128];
    for (int i = threadIdx.x; i < 640; i += 256) sC[i] = crcrp[i];
    for (int i = threadIdx.x; i < 128; i += 256) sAttn[i] = attn[i];
    __syncthreads();
    int warp = threadIdx.x >> 5, lane = threadIdx.x & 31;
    int node = blockIdx.x * 8 + warp;
    if (node >= NN) return;
    int q    = lane & 15;        // within-half lane
    int half = lane >> 4;        // stream id
    int ch   = q * 8;            // first of 8 channels owned by this lane
    int i0 = rowptr[node], i1 = rowptr[node + 1];
    float4 acc0 = make_float4(0.f, 0.f, 0.f, 0.f);
    float4 acc1 = make_float4(0.f, 0.f, 0.f, 0.f);
    float m = -1e30f, s = 0.f;
    if (i1 > i0) {
        // hoist per-lane channel constants to registers (once per node)
        float at[8], cc0[8], cc1[8], cc2[8], cc3[8], cc4[8];
#pragma unroll
        for (int j = 0; j < 8; j++) {
            at[j]  = sAttn[ch + j];
            cc0[j] = sC[ch + j];
            cc1[j] = sC[128 + ch + j];
            cc2[j] = sC[256 + ch + j];
            cc3[j] = sC[384 + ch + j];
            cc4[j] = sC[512 + ch + j];
        }
        float4 fj0 = *(const float4*)(hnj + (size_t)node * 128 + ch);
        float4 fj1 = *(const float4*)(hnj + (size_t)node * 128 + ch + 4);
        int nit = (i1 - i0 + 1) >> 1;
        for (int it = 0; it < nit; it++) {
            int idx = i0 + it * 2 + half;
            bool valid = (idx < i1);
            int idxc = valid ? idx : i0;
            unsigned int rec = edata[(size_t)idxc * 8 + (q & 7)];
            int base = half << 4;
            int   sn = (int)__shfl_sync(0xffffffffu, rec, base + 0);
            int   tr = (int)__shfl_sync(0xffffffffu, rec, base + 1);
            float a0 = __uint_as_float(__shfl_sync(0xffffffffu, rec, base + 2));
            float a1 = __uint_as_float(__shfl_sync(0xffffffffu, rec, base + 3));
            float p0 = __uint_as_float(__shfl_sync(0xffffffffu, rec, base + 4));
            float p1 = __uint_as_float(__shfl_sync(0xffffffffu, rec, base + 5));
            float p2 = __uint_as_float(__shfl_sync(0xffffffffu, rec, base + 6));
            float4 fi0 = *(const float4*)(hni   + (size_t)sn * 128 + ch);
            float4 fi1 = *(const float4*)(hni   + (size_t)sn * 128 + ch + 4);
            float4 v0  = *(const float4*)(hnode + (size_t)sn * 128 + ch);
            float4 v1  = *(const float4*)(hnode + (size_t)sn * 128 + ch + 4);
            float4 ft0 = *(const float4*)(table + (size_t)tr * 128 + ch);
            float4 ft1 = *(const float4*)(table + (size_t)tr * 128 + ch + 4);
            float x[8];
            x[0] = fi0.x + fj0.x + ft0.x; x[1] = fi0.y + fj0.y + ft0.y;
            x[2] = fi0.z + fj0.z + ft0.z; x[3] = fi0.w + fj0.w + ft0.w;
            x[4] = fi1.x + fj1.x + ft1.x; x[5] = fi1.y + fj1.y + ft1.y;
            x[6] = fi1.z + fj1.z + ft1.z; x[7] = fi1.w + fj1.w + ft1.w;
            float part = 0.f;
#pragma unroll
            for (int j = 0; j < 8; j++) {
                float xv = x[j] + a0 * cc0[j] + a1 * cc1[j]
                         + p0 * cc2[j] + p1 * cc3[j] + p2 * cc4[j];
                xv = (xv >= 0.f) ? xv : 0.2f * xv;
                part += xv * at[j];
            }
            // reduce within 8-lane head group (channels of one head)
            part += __shfl_xor_sync(0xffffffffu, part, 4);
            part += __shfl_xor_sync(0xffffffffu, part, 2);
            part += __shfl_xor_sync(0xffffffffu, part, 1);
            float e = valid ? part : -1e30f;
            // online softmax update (per stream, per head)
            float n  = fmaxf(m, e);
            float sc = __expf(m - n);
            float p  = valid ? __expf(e - n) : 0.f;
            s = s * sc + p;
            acc0.x = acc0.x * sc + p * v0.x;
            acc0.y = acc0.y * sc + p * v0.y;
            acc0.z = acc0.z * sc + p * v0.z;
            acc0.w = acc0.w * sc + p * v0.w;
            acc1.x = acc1.x * sc + p * v1.x;
            acc1.y = acc1.y * sc + p * v1.y;
            acc1.z = acc1.z * sc + p * v1.z;
            acc1.w = acc1.w * sc + p * v1.w;
            m = n;
        }
    }
    // merge the two streams (exact): partner lane = lane ^ 16
    float mo = __shfl_xor_sync(0xffffffffu, m, 16);
    float so = __shfl_xor_sync(0xffffffffu, s, 16);
    float o0x = __shfl_xor_sync(0xffffffffu, acc0.x, 16);
    float o0y = __shfl_xor_sync(0xffffffffu, acc0.y, 16);
    float o0z = __shfl_xor_sync(0xffffffffu, acc0.z, 16);
    float o0w = __shfl_xor_sync(0xffffffffu, acc0.w, 16);
    float o1x = __shfl_xor_sync(0xffffffffu, acc1.x, 16);
    float o1y = __shfl_xor_sync(0xffffffffu, acc1.y, 16);
    float o1z = __shfl_xor_sync(0xffffffffu, acc1.z, 16);
    float o1w = __shfl_xor_sync(0xffffffffu, acc1.w, 16);
    float n   = fmaxf(m, mo);
    float scs = __expf(m - n), sco = __expf(mo - n);
    float st  = s * scs + so * sco;
    float inv = 1.f / (st + 1e-9f);
    if (half == 0) {
        float4 r0, r1;
        r0.x = (acc0.x * scs + o0x * sco) * inv;
        r0.y = (acc0.y * scs + o0y * sco) * inv;
        r0.z = (acc0.z * scs + o0z * sco) * inv;
        r0.w = (acc0.w * scs + o0w * sco) * inv;
        r1.x = (acc1.x * scs + o1x * sco) * inv;
        r1.y = (acc1.y * scs + o1y * sco) * inv;
        r1.z = (acc1.z * scs + o1z * sco) * inv;
        r1.w = (acc1.w * scs + o1w * sco) * inv;
        *(float4*)(hatt + (size_t)node * 128 + ch)     = r0;
        *(float4*)(hatt + (size_t)node * 128 + ch + 4) = r1;
    }
}

// ---------------- graph max pooling (2-stage, reads out directly) -----------
__global__ void pool_part_k(const float* __restrict__ out, float* __restrict__ part) {
    int b = blockIdx.x, fc = blockIdx.y, sp = blockIdx.z;
    int fl = threadIdx.x & 63;
    int f  = fc * 64 + fl;
    int grp = threadIdx.x >> 6;
    int n0 = sp * PS, n1 = n0 + PS;
    if (n1 > NPG) n1 = NPG;
    float m = -1e30f;
    if (f < NFEAT) {
        const float* base = out + (size_t)b * NPG * OCOLS;
        for (int n = n0 + grp; n < n1; n += 4)
            m = fmaxf(m, base[(size_t)n * OCOLS + f]);
    }
    __shared__ float sm[256];
    sm[threadIdx.x] = m;
    __syncthreads();
    if (grp == 0) {
        m = fmaxf(fmaxf(sm[threadIdx.x], sm[threadIdx.x + 64]),
                  fmaxf(sm[threadIdx.x + 128], sm[threadIdx.x + 192]));
        part[((b * 5 + fc) * NSPLIT + sp) * 64 + fl] = m;
    }
}
__global__ void pool_reduce_k(const float* __restrict__ part, float* __restrict__ gmax) {
    int b = blockIdx.x, fc = blockIdx.y, t = threadIdx.x;   // block 64
    float m = -1e30f;
#pragma unroll
    for (int sp = 0; sp < NSPLIT; sp++)
        m = fmaxf(m, part[((b * 5 + fc) * NSPLIT + sp) * 64 + t]);
    int f = fc * 64 + t;
    if (f < NFEAT) gmax[b * NFEAT + f] = m;
}

// fill the broadcast half: out[:, 266..531] = gmax[b]
__global__ void write_rep_k(const float* __restrict__ gmax, float* __restrict__ out) {
    long long idx = (long long)blockIdx.x * 256 + threadIdx.x;
    const long long total = (long long)NB * NPG * NFEAT;
    if (idx >= total) return;
    int cl = (int)(idx % NFEAT);
    long long bn = idx / NFEAT;
    int b = (int)(bn / NPG);
    out[bn * OCOLS + NFEAT + cl] = gmax[b * NFEAT + cl];
}

// ---------------- host launcher ----------------
extern "C" void kernel_launch(void* const* d_in, const int* in_sizes, int n_in,
                              void* d_out, int out_size)
{
    const float* feat      = (const float*)d_in[0];
    const float* att_rc    = (const float*)d_in[1];
    const float* att_rp    = (const float*)d_in[2];
    const float* etype_emb = (const float*)d_in[3];
    const float* rid_emb   = (const float*)d_in[4];
    const float* rc_W      = (const float*)d_in[5];
    const float* rc_b      = (const float*)d_in[6];
    const float* rp_W      = (const float*)d_in[7];
    const float* rp_b      = (const float*)d_in[8];
    const float* fe_W0     = (const float*)d_in[9];
    const float* fe_b0     = (const float*)d_in[10];
    const float* fe_W1     = (const float*)d_in[11];
    const float* fe_b1     = (const float*)d_in[12];
    const float* W_ni      = (const float*)d_in[13];
    const float* W_nj      = (const float*)d_in[14];
    const float* W_fij     = (const float*)d_in[15];
    const float* W_node    = (const float*)d_in[16];
    const float* attn      = (const float*)d_in[17];
    const float* egat_bias = (const float*)d_in[18];
    const float* Wm0       = (const float*)d_in[19];
    const float* bm0       = (const float*)d_in[20];
    const float* Wm1       = (const float*)d_in[21];
    const float* bm1       = (const float*)d_in[22];
    const int*   src       = (const int*)d_in[23];
    const int*   dst       = (const int*)d_in[24];
    const int*   etype     = (const int*)d_in[25];
    const int*   rid       = (const int*)d_in[26];
    float* out = (float*)d_out;

    float *p_h, *p_hni, *p_hnj, *p_hnode, *p_hatt;
    float *p_table, *p_crcrp, *p_gmax, *p_pool;
    int *p_deg, *p_rowptr, *p_cursor, *p_bsum;
    unsigned int* p_edata;
    cudaGetSymbolAddress((void**)&p_h,      g_h);
    cudaGetSymbolAddress((void**)&p_hni,    g_hni);
    cudaGetSymbolAddress((void**)&p_hnj,    g_hnj);
    cudaGetSymbolAddress((void**)&p_hnode,  g_hnode);
    cudaGetSymbolAddress((void**)&p_hatt,   g_hatt);
    cudaGetSymbolAddress((void**)&p_table,  g_table);
    cudaGetSymbolAddress((void**)&p_crcrp,  g_crcrp);
    cudaGetSymbolAddress((void**)&p_gmax,   g_gmax);
    cudaGetSymbolAddress((void**)&p_pool,   g_pool);
    cudaGetSymbolAddress((void**)&p_deg,    g_deg);
    cudaGetSymbolAddress((void**)&p_rowptr, g_rowptr);
    cudaGetSymbolAddress((void**)&p_cursor, g_cursor);
    cudaGetSymbolAddress((void**)&p_bsum,   g_bsum);
    cudaGetSymbolAddress((void**)&p_edata,  g_edata);

    const int SH_PROJ = (128 * LDA_P + 64 * LDW_P) * 4;    // ~68.6 KB
    const int SH_MLP  = (128 * LDH_M * 2) * 4;             // ~135 KB
    cudaFuncSetAttribute((const void*)proj3_k,
                         cudaFuncAttributeMaxDynamicSharedMemorySize, SH_PROJ);
    cudaFuncSetAttribute((const void*)mlp_fused_k,
                         cudaFuncAttributeMaxDynamicSharedMemorySize, SH_MLP);

    const int GRID_T = (NN + 127) / 128;    // 391 (tf32 tiles)
    const int GRID_E = (EE + 255) / 256;    // 1954
    const int NBLK_SCAN = (NN + 255) / 256; // 196

    // 1) feature encoder (writes out cols 0..73)
    fe_mlp_k<<<(NN + 255) / 256, 256>>>(feat, fe_W0, fe_b0, fe_W1, fe_b1, p_h, out);

    // 2) CSR by dst (parallel scan) + packed edge records
    zero_int_k<<<NBLK_SCAN, 256>>>(p_deg, NN);
    hist_k<<<GRID_E, 256>>>(dst, p_deg);
    scan_partial_k<<<NBLK_SCAN, 256>>>(p_deg, p_bsum);
    scan_bsum_k<<<1, 256>>>(p_bsum, NBLK_SCAN);
    scan_final_k<<<NBLK_SCAN, 256>>>(p_deg, p_bsum, p_rowptr, p_cursor);
    scatter_k<<<GRID_E, 256>>>(dst, src, etype, rid, att_rc, att_rp, p_cursor, p_edata);

    // 3) EGAT layers
    for (int l = 0; l < 3; l++) {
        precompute_fij_k<<<222, 128>>>(etype_emb, rid_emb, rc_W, rp_W, rc_b, rp_b,
                                       W_fij + l * 64 * 128, egat_bias + l * 128,
                                       p_table, p_crcrp);
        proj3_k<<<dim3(GRID_T, 3), 256, SH_PROJ>>>(
            p_h, W_ni + l * 64 * 128, W_nj + l * 64 * 128, W_node + l * 64 * 128,
            p_hni, p_hnj, p_hnode, NN);

        attn_agg_k<<<NN / 8, 256>>>(p_hni, p_hnj, p_hnode, p_table, p_crcrp,
                                    attn + l * 128, p_rowptr, p_edata, p_hatt);

        mlp_fused_k<<<GRID_T, 256, SH_MLP>>>(
            p_hatt, Wm0 + l * 128 * 128, bm0 + l * 128,
            Wm1 + l * 128 * 64, bm1 + l * 64,
            p_h, out, 10 + 64 * (l + 1), NN);
    }

    // 4) pooling (2-stage, reads out) + broadcast fill
    pool_part_k<<<dim3(NB, 5, NSPLIT), 256>>>(out, p_pool);
    pool_reduce_k<<<dim3(NB, 5), 64>>>(p_pool, p_gmax);
    long long total = (long long)NB * NPG * NFEAT;
    write_rep_k<<<(int)((total + 255) / 256), 256>>>(p_gmax, out);
}